// round 7
// baseline (speedup 1.0000x reference)
#include <cuda_runtime.h>

// TT embedding lookup, GB300 sm_103a — i1-deduplicated bucketed version, v2.
// v2 fix: sItems compaction is now a STABLE j-ordered ballot scan (the v1
// atomicAdd ordering differed across the YDIM sibling CTAs, breaking the
// position-based work partition -> some samples never computed).
//
// Shapes: lS_i [2,1024] (int32 OR int64 -- runtime-probed);
//         core0 [2,216,256] f32; core1 [2,216,65536] f32;
//         core2 [2,216,256] f32; out [2,1024,16] f32.
// out[q0,q1,q2] = sum_{r0,r1} A[q0,r0] * Bm[r0,q1,r1] * C[r1,q2]
//   A  = core0 row, flat q0*128 + r0
//   Bm = core1 row, flat r0*512 + q1*128 + r1   (256 KB -- dominant gather)
//   C  = core2 row, flat r1*2 + q2

#define NTAB   2
#define BATCH  1024
#define PDIM   216
#define P12    46656
#define GSIZE  3      // samples per row pass (register-resident)
#define YDIM   4      // group-parallel CTAs per bucket

__device__ int g_idx_is64;   // 1 if lS_i is int64, 0 if int32

__global__ void probe_dtype_kernel(const int* __restrict__ raw)
{
    int is64 = 1;
#pragma unroll
    for (int k = 0; k < 32; k++)
        if (raw[2 * k + 1] != 0) is64 = 0;
    g_idx_is64 = is64;
}

// ---- packed f32x2 helpers ------------------------------------------------
typedef unsigned long long u64t;

__device__ __forceinline__ u64t pack2(float lo, float hi) {
    u64t r; asm("mov.b64 %0,{%1,%2};" : "=l"(r) : "f"(lo), "f"(hi)); return r;
}
__device__ __forceinline__ u64t dup2(float x) { return pack2(x, x); }
__device__ __forceinline__ u64t mul2(u64t a, u64t b) {
    u64t d; asm("mul.rn.f32x2 %0,%1,%2;" : "=l"(d) : "l"(a), "l"(b)); return d;
}
__device__ __forceinline__ u64t fma2(u64t a, u64t b, u64t c) {
    u64t d; asm("fma.rn.f32x2 %0,%1,%2,%3;" : "=l"(d) : "l"(a), "l"(b), "l"(c)); return d;
}
__device__ __forceinline__ u64t add2(u64t a, u64t b) {
    u64t d; asm("add.rn.f32x2 %0,%1,%2;" : "=l"(d) : "l"(a), "l"(b)); return d;
}
__device__ __forceinline__ void unpack2(u64t v, float& lo, float& hi) {
    asm("mov.b64 {%0,%1},%2;" : "=f"(lo), "=f"(hi) : "l"(v));
}

__global__ __launch_bounds__(128)
void tt_bucket_kernel(const void* __restrict__ lS_i_raw,
                      const float* __restrict__ core0,
                      const float* __restrict__ core1,
                      const float* __restrict__ core2,
                      float* __restrict__ out)
{
    const int tb   = blockIdx.x;          // bucket: t*216 + i1
    const int t    = tb / PDIM;
    const int i1   = tb - t * PDIM;
    const int tid  = threadIdx.x;
    const int warp = tid >> 5;
    const int lane = tid & 31;

    __shared__ int   sWcnt[4];
    __shared__ int   sBase;
    __shared__ int   sItems[BATCH];             // packed: b | i0<<10 | i2<<18
    __shared__ float sA[GSIZE][256];            // A rows for current group
    __shared__ float sOut[4][GSIZE][16];        // per-warp partials

    if (tid == 0) sBase = 0;
    __syncthreads();

    // ---- stable j-ordered compaction of this bucket's samples -------------
    // Position of each match is a pure function of j => identical ordering in
    // every sibling CTA (blockIdx.y) and every run.
    {
        const int is64 = g_idx_is64;
        const int* raw = (const int*)lS_i_raw;
        for (int jb = 0; jb < BATCH; jb += 128) {
            const int j   = jb + tid;
            const int pos = t * BATCH + j;
            int v = is64 ? raw[2 * pos] : raw[pos];   // idx < 1e7 < 2^31
            v = max(v, 0);
            int i0  = v / P12;
            int rem = v - i0 * P12;
            int a   = rem / PDIM;
            int i2  = rem - a * PDIM;
            i0 = min(i0, PDIM - 1);
            const bool m = (a == i1);
            const unsigned mask = __ballot_sync(0xffffffffu, m);
            if (lane == 0) sWcnt[warp] = __popc(mask);
            __syncthreads();
            int wbase = sBase;
            for (int w = 0; w < warp; w++) wbase += sWcnt[w];
            if (m) {
                const int rank = __popc(mask & ((1u << lane) - 1u));
                sItems[wbase + rank] = j | (i0 << 10) | (i2 << 18);
            }
            __syncthreads();
            if (tid == 0)
                sBase += sWcnt[0] + sWcnt[1] + sWcnt[2] + sWcnt[3];
            __syncthreads();
        }
    }
    const int S = sBase;

    const float4* Brow = (const float4*)(core1 + ((size_t)tb) * 65536);

    for (int base = blockIdx.y * GSIZE; base < S; base += gridDim.y * GSIZE) {
        const int cnt = min(GSIZE, S - base);

        // ---- stage A rows for the group (coalesced) -----------------------
#pragma unroll
        for (int s = 0; s < GSIZE; s++) {
            if (s < cnt) {
                const int it = sItems[base + s];
                const int i0 = (it >> 10) & 255;
                const float* Arow = core0 + ((size_t)t * PDIM + i0) * 256;
                sA[s][tid]       = Arow[tid];
                sA[s][tid + 128] = Arow[tid + 128];
            }
        }
        __syncthreads();

        // ---- per-lane C chunks: r1 in [lane*4, lane*4+4), packed (q2=0,q2=1)
        u64t cs[GSIZE][4];
#pragma unroll
        for (int s = 0; s < GSIZE; s++) {
            if (s < cnt) {
                const int it = sItems[base + s];
                const int i2 = (it >> 18) & 255;
                const float4* Crow =
                    (const float4*)(core2 + ((size_t)t * PDIM + i2) * 256);
                const float4 cv0 = Crow[lane * 2 + 0];
                const float4 cv1 = Crow[lane * 2 + 1];
                cs[s][0] = pack2(cv0.x, cv0.y);
                cs[s][1] = pack2(cv0.z, cv0.w);
                cs[s][2] = pack2(cv1.x, cv1.y);
                cs[s][3] = pack2(cv1.z, cv1.w);
            } else {
                cs[s][0] = cs[s][1] = cs[s][2] = cs[s][3] = 0ULL;
            }
        }

        // ---- main contraction: one row pass for the whole group -----------
        // acc[s][q0*4+q1] = packed (out[q0,q1,0], out[q0,q1,1]) partial
        u64t acc[GSIZE][8];
#pragma unroll
        for (int s = 0; s < GSIZE; s++)
#pragma unroll
            for (int k = 0; k < 8; k++) acc[s][k] = 0ULL;

        for (int r0 = warp; r0 < 128; r0 += 4) {
            const float4* bp = Brow + r0 * 128;
            u64t a0p[GSIZE], a1p[GSIZE];
#pragma unroll
            for (int s = 0; s < GSIZE; s++) {
                a0p[s] = dup2(sA[s][r0]);          // LDS broadcast
                a1p[s] = dup2(sA[s][128 + r0]);
            }
#pragma unroll
            for (int q1 = 0; q1 < 4; q1++) {
                const float4 bv = bp[q1 * 32 + lane];   // coalesced LDG.128
                const u64t bx = dup2(bv.x), by = dup2(bv.y);
                const u64t bz = dup2(bv.z), bw = dup2(bv.w);
#pragma unroll
                for (int s = 0; s < GSIZE; s++) {
                    u64t tp = mul2(bx, cs[s][0]);
                    tp = fma2(by, cs[s][1], tp);
                    tp = fma2(bz, cs[s][2], tp);
                    tp = fma2(bw, cs[s][3], tp);
                    acc[s][q1]     = fma2(a0p[s], tp, acc[s][q1]);
                    acc[s][4 + q1] = fma2(a1p[s], tp, acc[s][4 + q1]);
                }
            }
        }

        // ---- intra-warp butterfly reduction (packed adds) -----------------
#pragma unroll
        for (int off = 16; off; off >>= 1) {
#pragma unroll
            for (int s = 0; s < GSIZE; s++)
#pragma unroll
                for (int k = 0; k < 8; k++)
                    acc[s][k] = add2(acc[s][k],
                                     __shfl_xor_sync(0xffffffffu, acc[s][k], off));
        }

        if (lane == 0) {
#pragma unroll
            for (int s = 0; s < GSIZE; s++)
#pragma unroll
                for (int k = 0; k < 8; k++) {
                    float lo, hi;
                    unpack2(acc[s][k], lo, hi);
                    sOut[warp][s][2 * k]     = lo;
                    sOut[warp][s][2 * k + 1] = hi;
                }
        }
        __syncthreads();

        // ---- cross-warp sum + store --------------------------------------
        if (tid < cnt * 16) {
            const int s = tid >> 4;
            const int k = tid & 15;
            const float v = sOut[0][s][k] + sOut[1][s][k]
                          + sOut[2][s][k] + sOut[3][s][k];
            const int b = sItems[base + s] & 1023;
            out[((size_t)(t * BATCH + b)) * 16 + k] = v;
        }
        __syncthreads();   // protect sA/sOut before next group iteration
    }
}

extern "C" void kernel_launch(void* const* d_in, const int* in_sizes, int n_in,
                              void* d_out, int out_size)
{
    const void*  lS_i  = d_in[0];
    const float* core0 = (const float*)d_in[1];
    const float* core1 = (const float*)d_in[2];
    const float* core2 = (const float*)d_in[3];
    float*       out   = (float*)d_out;

    probe_dtype_kernel<<<1, 1>>>((const int*)lS_i);

    dim3 grid(NTAB * PDIM, YDIM);
    tt_bucket_kernel<<<grid, 128>>>(lS_i, core0, core1, core2, out);
}

// round 9
// speedup vs baseline: 1.1300x; 1.1300x over previous
#include <cuda_runtime.h>

// TT embedding lookup, GB300 sm_103a — v3: one CTA per (table,i1) bucket,
// core1 row streamed ONCE per bucket via 3-stage cp.async smem pipeline,
// warp-per-2-samples consuming tiles from smem. gmem reads ~110 MB (floor).
//
// Shapes: lS_i [2,1024] (int32 OR int64, runtime-probed);
//         core0 [2,216,256] f32; core1 [2,216,65536] f32;
//         core2 [2,216,256] f32; out [2,1024,16] f32.
// out[q0,q1,q2] = sum_{r0,r1} A[q0*128+r0] * Bm[r0*512+q1*128+r1] * C[r1*2+q2]

#define NTAB    2
#define BATCH   1024
#define PDIM    216
#define P12     46656
#define NTHR    256
#define CHUNK   16                 // samples per row pass (8 warps x 2)
#define TILE_R0 4                  // r0 rows per tile
#define TILE_F4 (TILE_R0 * 128)    // 512 float4 = 8 KB per tile
#define NTILE   (128 / TILE_R0)    // 32 tiles per row
#define NSTAGE  3

__device__ int g_idx_is64;   // 1 if lS_i is int64, 0 if int32

__global__ void probe_dtype_kernel(const int* __restrict__ raw)
{
    int is64 = 1;
#pragma unroll
    for (int k = 0; k < 32; k++)
        if (raw[2 * k + 1] != 0) is64 = 0;
    g_idx_is64 = is64;
}

// ---- packed f32x2 helpers ------------------------------------------------
typedef unsigned long long u64t;

__device__ __forceinline__ u64t pack2(float lo, float hi) {
    u64t r; asm("mov.b64 %0,{%1,%2};" : "=l"(r) : "f"(lo), "f"(hi)); return r;
}
__device__ __forceinline__ u64t dup2(float x) { return pack2(x, x); }
__device__ __forceinline__ u64t mul2(u64t a, u64t b) {
    u64t d; asm("mul.rn.f32x2 %0,%1,%2;" : "=l"(d) : "l"(a), "l"(b)); return d;
}
__device__ __forceinline__ u64t fma2(u64t a, u64t b, u64t c) {
    u64t d; asm("fma.rn.f32x2 %0,%1,%2,%3;" : "=l"(d) : "l"(a), "l"(b), "l"(c)); return d;
}
__device__ __forceinline__ u64t add2(u64t a, u64t b) {
    u64t d; asm("add.rn.f32x2 %0,%1,%2;" : "=l"(d) : "l"(a), "l"(b)); return d;
}

// ---- cp.async tile copy: 512 float4, 256 threads x 2 ---------------------
__device__ __forceinline__ void cp_tile(const float4* __restrict__ gsrc,
                                        float4* sdst, int tid)
{
#pragma unroll
    for (int u = 0; u < TILE_F4 / NTHR; u++) {
        const int idx = u * NTHR + tid;
        unsigned d = (unsigned)__cvta_generic_to_shared(sdst + idx);
        asm volatile("cp.async.cg.shared.global [%0], [%1], 16;"
                     :: "r"(d), "l"(gsrc + idx) : "memory");
    }
}
#define CP_COMMIT() asm volatile("cp.async.commit_group;" ::: "memory")
#define CP_WAIT1()  asm volatile("cp.async.wait_group 1;" ::: "memory")

__global__ __launch_bounds__(NTHR, 3)
void tt_row_kernel(const void* __restrict__ lS_i_raw,
                   const float* __restrict__ core0,
                   const float* __restrict__ core1,
                   const float* __restrict__ core2,
                   float* __restrict__ out)
{
    const int tb   = blockIdx.x;          // bucket: t*216 + i1
    const int t    = tb / PDIM;
    const int i1   = tb - t * PDIM;
    const int tid  = threadIdx.x;
    const int warp = tid >> 5;
    const int lane = tid & 31;

    __shared__ int    sCnt;
    __shared__ int    sItems[BATCH];            // packed: b | i0<<10 | i2<<18
    __shared__ float  sA[CHUNK][256];           // A rows for current chunk (16 KB)
    __shared__ float4 sB[NSTAGE][TILE_F4];      // pipelined B tiles (24 KB)

    if (tid == 0) sCnt = 0;
    __syncthreads();

    // ---- scan this table's indices for bucket i1 --------------------------
    // atomicAdd compaction order is nondeterministic but harmless: each
    // sample's value is computed independently with a fixed reduction order.
    {
        const int is64 = g_idx_is64;
        const int* raw = (const int*)lS_i_raw;
        for (int j = tid; j < BATCH; j += NTHR) {
            const int pos = t * BATCH + j;
            int v = is64 ? raw[2 * pos] : raw[pos];   // idx < 1e7 < 2^31
            v = max(v, 0);
            int i0  = v / P12;
            int rem = v - i0 * P12;
            int a   = rem / PDIM;
            int i2  = rem - a * PDIM;
            i0 = min(i0, PDIM - 1);
            if (a == i1) {
                int p = atomicAdd(&sCnt, 1);
                sItems[p] = j | (i0 << 10) | (i2 << 18);
            }
        }
    }
    __syncthreads();
    const int S = sCnt;
    if (S == 0) return;   // CTA-uniform exit

    const float4* BrowF4 = (const float4*)(core1 + (size_t)tb * 65536);

    for (int base = 0; base < S; base += CHUNK) {
        const int nc = min(CHUNK, S - base);

        // ---- stage A rows (coalesced: 256 thr = 1 row per iteration) ------
        for (int s = 0; s < nc; s++) {
            const int it = sItems[base + s];
            const int i0 = (it >> 10) & 255;
            sA[s][tid] = core0[((size_t)t * PDIM + i0) * 256 + tid];
        }

        // ---- this warp's 2 samples; per-lane C chunks (r1 in [4l,4l+4)) ---
        const int  s0l = 2 * warp, s1l = s0l + 1;
        const bool h0  = s0l < nc;
        const bool h1  = s1l < nc;

        u64t cs0[4], cs1[4];
#pragma unroll
        for (int j = 0; j < 4; j++) { cs0[j] = 0ULL; cs1[j] = 0ULL; }
        if (h0) {
            const int i2 = (sItems[base + s0l] >> 18) & 255;
            const float4* Crow = (const float4*)(core2 + ((size_t)t * PDIM + i2) * 256);
            const float4 c0 = Crow[lane * 2], c1 = Crow[lane * 2 + 1];
            cs0[0] = pack2(c0.x, c0.y); cs0[1] = pack2(c0.z, c0.w);
            cs0[2] = pack2(c1.x, c1.y); cs0[3] = pack2(c1.z, c1.w);
        }
        if (h1) {
            const int i2 = (sItems[base + s1l] >> 18) & 255;
            const float4* Crow = (const float4*)(core2 + ((size_t)t * PDIM + i2) * 256);
            const float4 c0 = Crow[lane * 2], c1 = Crow[lane * 2 + 1];
            cs1[0] = pack2(c0.x, c0.y); cs1[1] = pack2(c0.z, c0.w);
            cs1[2] = pack2(c1.x, c1.y); cs1[3] = pack2(c1.z, c1.w);
        }

        u64t acc0[8], acc1[8];
#pragma unroll
        for (int k2 = 0; k2 < 8; k2++) { acc0[k2] = 0ULL; acc1[k2] = 0ULL; }

        __syncthreads();   // sA ready; previous chunk's smem use complete

        // ---- pipeline prologue: 2 tiles in flight -------------------------
        cp_tile(BrowF4,            &sB[0][0], tid); CP_COMMIT();
        cp_tile(BrowF4 + TILE_F4,  &sB[1][0], tid); CP_COMMIT();

        for (int k = 0; k < NTILE; k++) {
            CP_WAIT1();          // tile k arrived (<=1 newer group pending)
            __syncthreads();     // all warps see tile k; buf (k+2)%3 free
            if (k + 2 < NTILE)
                cp_tile(BrowF4 + (size_t)(k + 2) * TILE_F4,
                        &sB[(k + 2) % NSTAGE][0], tid);
            CP_COMMIT();         // empty group on tail iterations is legal

            if (h0) {            // warp-uniform: sample-less warps skip
                const float4* bt = &sB[k % NSTAGE][0];
#pragma unroll
                for (int r = 0; r < TILE_R0; r++) {
                    const int r0 = k * TILE_R0 + r;
                    const u64t a00 = dup2(sA[s0l][r0]);
                    const u64t a01 = dup2(sA[s0l][128 + r0]);
                    const u64t a10 = dup2(h1 ? sA[s1l][r0] : 0.f);
                    const u64t a11 = dup2(h1 ? sA[s1l][128 + r0] : 0.f);
#pragma unroll
                    for (int q1 = 0; q1 < 4; q1++) {
                        const float4 bv = bt[r * 128 + q1 * 32 + lane]; // conflict-free LDS.128
                        const u64t bx = dup2(bv.x), by = dup2(bv.y);
                        const u64t bz = dup2(bv.z), bw = dup2(bv.w);
                        u64t tp0 = mul2(bx, cs0[0]);
                        tp0 = fma2(by, cs0[1], tp0);
                        tp0 = fma2(bz, cs0[2], tp0);
                        tp0 = fma2(bw, cs0[3], tp0);
                        acc0[q1]     = fma2(a00, tp0, acc0[q1]);
                        acc0[4 + q1] = fma2(a01, tp0, acc0[4 + q1]);
                        u64t tp1 = mul2(bx, cs1[0]);
                        tp1 = fma2(by, cs1[1], tp1);
                        tp1 = fma2(bz, cs1[2], tp1);
                        tp1 = fma2(bw, cs1[3], tp1);
                        acc1[q1]     = fma2(a10, tp1, acc1[q1]);
                        acc1[4 + q1] = fma2(a11, tp1, acc1[4 + q1]);
                    }
                }
            }
        }

        // ---- butterfly reduce within warp, then store ---------------------
        if (h0) {
#pragma unroll
            for (int off = 16; off; off >>= 1) {
#pragma unroll
                for (int k2 = 0; k2 < 8; k2++) {
                    acc0[k2] = add2(acc0[k2], __shfl_xor_sync(0xffffffffu, acc0[k2], off));
                    acc1[k2] = add2(acc1[k2], __shfl_xor_sync(0xffffffffu, acc1[k2], off));
                }
            }
            if (lane == 0) {
                {
                    const int b = sItems[base + s0l] & 1023;
                    u64t* op = (u64t*)(out + ((size_t)(t * BATCH + b)) * 16);
#pragma unroll
                    for (int k2 = 0; k2 < 8; k2++) op[k2] = acc0[k2];
                }
                if (h1) {
                    const int b = sItems[base + s1l] & 1023;
                    u64t* op = (u64t*)(out + ((size_t)(t * BATCH + b)) * 16);
#pragma unroll
                    for (int k2 = 0; k2 < 8; k2++) op[k2] = acc1[k2];
                }
            }
        }
        __syncthreads();   // protect sA/sB before next chunk
    }
}

extern "C" void kernel_launch(void* const* d_in, const int* in_sizes, int n_in,
                              void* d_out, int out_size)
{
    const void*  lS_i  = d_in[0];
    const float* core0 = (const float*)d_in[1];
    const float* core1 = (const float*)d_in[2];
    const float* core2 = (const float*)d_in[3];
    float*       out   = (float*)d_out;

    probe_dtype_kernel<<<1, 1>>>((const int*)lS_i);
    tt_row_kernel<<<NTAB * PDIM, NTHR>>>(lS_i, core0, core1, core2, out);
}

// round 10
// speedup vs baseline: 1.2771x; 1.1302x over previous
#include <cuda_runtime.h>

// TT embedding lookup, GB300 sm_103a — v5: i1-bucketed, GSIZE=2 row sharing,
// f32x2 math, stable ballot compaction, double-buffered B prefetch.
// Lesson history: R3 gather sustained 11.4 TB/s L2 @ 27 warps/SM; R7 (GSIZE=3,
// 132 regs, occ 18.5%) collapsed to 3.5 TB/s; v3 tile pipeline throttled the
// DRAM stream via warp imbalance. v5 = R3 structure + dedup x2 + reg headroom.
//
// out[q0,q1,q2] = sum_{r0,r1} A[q0*128+r0] * Bm[r0*512+q1*128+r1] * C[r1*2+q2]

#define NTAB   2
#define BATCH  1024
#define PDIM   216
#define P12    46656
#define GSIZE  2      // samples per row pass
#define YDIM   3      // group-parallel CTAs per bucket

__device__ int g_idx_is64;   // 1 if lS_i is int64, 0 if int32

__global__ void probe_dtype_kernel(const int* __restrict__ raw)
{
    int is64 = 1;
#pragma unroll
    for (int k = 0; k < 32; k++)
        if (raw[2 * k + 1] != 0) is64 = 0;
    g_idx_is64 = is64;
}

// ---- packed f32x2 helpers ------------------------------------------------
typedef unsigned long long u64t;

__device__ __forceinline__ u64t pack2(float lo, float hi) {
    u64t r; asm("mov.b64 %0,{%1,%2};" : "=l"(r) : "f"(lo), "f"(hi)); return r;
}
__device__ __forceinline__ u64t dup2(float x) { return pack2(x, x); }
__device__ __forceinline__ u64t mul2(u64t a, u64t b) {
    u64t d; asm("mul.rn.f32x2 %0,%1,%2;" : "=l"(d) : "l"(a), "l"(b)); return d;
}
__device__ __forceinline__ u64t fma2(u64t a, u64t b, u64t c) {
    u64t d; asm("fma.rn.f32x2 %0,%1,%2,%3;" : "=l"(d) : "l"(a), "l"(b), "l"(c)); return d;
}
__device__ __forceinline__ u64t add2(u64t a, u64t b) {
    u64t d; asm("add.rn.f32x2 %0,%1,%2;" : "=l"(d) : "l"(a), "l"(b)); return d;
}
__device__ __forceinline__ void unpack2(u64t v, float& lo, float& hi) {
    asm("mov.b64 {%0,%1},%2;" : "=f"(lo), "=f"(hi) : "l"(v));
}

__global__ __launch_bounds__(128, 5)
void tt_bucket_kernel(const void* __restrict__ lS_i_raw,
                      const float* __restrict__ core0,
                      const float* __restrict__ core1,
                      const float* __restrict__ core2,
                      float* __restrict__ out)
{
    const int tb   = blockIdx.x;          // bucket: t*216 + i1
    const int t    = tb / PDIM;
    const int i1   = tb - t * PDIM;
    const int tid  = threadIdx.x;
    const int warp = tid >> 5;
    const int lane = tid & 31;

    __shared__ int   sWcnt[4];
    __shared__ int   sBase;
    __shared__ int   sItems[BATCH];             // packed: b | i0<<10 | i2<<18
    __shared__ float sA[GSIZE][256];            // A rows for current group
    __shared__ float sOut[4][GSIZE][16];        // per-warp partials

    if (tid == 0) sBase = 0;
    __syncthreads();

    // ---- stable j-ordered compaction (identical across sibling CTAs) -----
    {
        const int is64 = g_idx_is64;
        const int* raw = (const int*)lS_i_raw;
        for (int jb = 0; jb < BATCH; jb += 128) {
            const int j   = jb + tid;
            const int pos = t * BATCH + j;
            int v = is64 ? raw[2 * pos] : raw[pos];   // idx < 1e7 < 2^31
            v = max(v, 0);
            int i0  = v / P12;
            int rem = v - i0 * P12;
            int a   = rem / PDIM;
            int i2  = rem - a * PDIM;
            i0 = min(i0, PDIM - 1);
            const bool m = (a == i1);
            const unsigned mask = __ballot_sync(0xffffffffu, m);
            if (lane == 0) sWcnt[warp] = __popc(mask);
            __syncthreads();
            int wbase = sBase;
            for (int w = 0; w < warp; w++) wbase += sWcnt[w];
            if (m) {
                const int rank = __popc(mask & ((1u << lane) - 1u));
                sItems[wbase + rank] = j | (i0 << 10) | (i2 << 18);
            }
            __syncthreads();
            if (tid == 0)
                sBase += sWcnt[0] + sWcnt[1] + sWcnt[2] + sWcnt[3];
            __syncthreads();
        }
    }
    const int S = sBase;

    const float4* Brow = (const float4*)(core1 + ((size_t)tb) * 65536);

    for (int base = blockIdx.y * GSIZE; base < S; base += gridDim.y * GSIZE) {
        const int cnt = min(GSIZE, S - base);

        // ---- stage A rows (coalesced) ------------------------------------
#pragma unroll
        for (int s = 0; s < GSIZE; s++) {
            if (s < cnt) {
                const int it = sItems[base + s];
                const int i0 = (it >> 10) & 255;
                const float* Arow = core0 + ((size_t)t * PDIM + i0) * 256;
                sA[s][tid]       = Arow[tid];
                sA[s][tid + 128] = Arow[tid + 128];
            }
        }
        __syncthreads();

        // ---- per-lane C chunks: r1 in [lane*4, lane*4+4), packed q2 pair --
        u64t cs0[4], cs1[4];
#pragma unroll
        for (int j = 0; j < 4; j++) { cs0[j] = 0ULL; cs1[j] = 0ULL; }
        {
            const int it = sItems[base];
            const int i2 = (it >> 18) & 255;
            const float4* Crow = (const float4*)(core2 + ((size_t)t * PDIM + i2) * 256);
            const float4 c0 = Crow[lane * 2], c1 = Crow[lane * 2 + 1];
            cs0[0] = pack2(c0.x, c0.y); cs0[1] = pack2(c0.z, c0.w);
            cs0[2] = pack2(c1.x, c1.y); cs0[3] = pack2(c1.z, c1.w);
        }
        if (cnt > 1) {
            const int it = sItems[base + 1];
            const int i2 = (it >> 18) & 255;
            const float4* Crow = (const float4*)(core2 + ((size_t)t * PDIM + i2) * 256);
            const float4 c0 = Crow[lane * 2], c1 = Crow[lane * 2 + 1];
            cs1[0] = pack2(c0.x, c0.y); cs1[1] = pack2(c0.z, c0.w);
            cs1[2] = pack2(c1.x, c1.y); cs1[3] = pack2(c1.z, c1.w);
        }
        // note: cnt==1 -> cs1=0 -> tp1=0 -> acc1 += a*0 = 0 (never stored)

        u64t acc0[8], acc1[8];
#pragma unroll
        for (int k = 0; k < 8; k++) { acc0[k] = 0ULL; acc1[k] = 0ULL; }

        // ---- contraction, double-buffered B loads (warp owns r0 % 4) -----
        float4 bv[4], bq[4];
        {
            const float4* bp = Brow + warp * 128;
#pragma unroll
            for (int q1 = 0; q1 < 4; q1++) bv[q1] = bp[q1 * 32 + lane];
        }
        for (int r0 = warp; r0 < 128; r0 += 4) {
            if (r0 + 4 < 128) {
                const float4* bpn = Brow + (r0 + 4) * 128;
#pragma unroll
                for (int q1 = 0; q1 < 4; q1++) bq[q1] = bpn[q1 * 32 + lane];
            }
            const u64t a00 = dup2(sA[0][r0]);
            const u64t a01 = dup2(sA[0][128 + r0]);
            const u64t a10 = dup2(sA[1][r0]);
            const u64t a11 = dup2(sA[1][128 + r0]);
#pragma unroll
            for (int q1 = 0; q1 < 4; q1++) {
                const u64t bx = dup2(bv[q1].x), by = dup2(bv[q1].y);
                const u64t bz = dup2(bv[q1].z), bw = dup2(bv[q1].w);
                u64t tp0 = mul2(bx, cs0[0]);
                tp0 = fma2(by, cs0[1], tp0);
                tp0 = fma2(bz, cs0[2], tp0);
                tp0 = fma2(bw, cs0[3], tp0);
                acc0[q1]     = fma2(a00, tp0, acc0[q1]);
                acc0[4 + q1] = fma2(a01, tp0, acc0[4 + q1]);
                u64t tp1 = mul2(bx, cs1[0]);
                tp1 = fma2(by, cs1[1], tp1);
                tp1 = fma2(bz, cs1[2], tp1);
                tp1 = fma2(bw, cs1[3], tp1);
                acc1[q1]     = fma2(a10, tp1, acc1[q1]);
                acc1[4 + q1] = fma2(a11, tp1, acc1[4 + q1]);
            }
#pragma unroll
            for (int q1 = 0; q1 < 4; q1++) bv[q1] = bq[q1];
        }

        // ---- intra-warp butterfly reduction ------------------------------
#pragma unroll
        for (int off = 16; off; off >>= 1) {
#pragma unroll
            for (int k = 0; k < 8; k++) {
                acc0[k] = add2(acc0[k], __shfl_xor_sync(0xffffffffu, acc0[k], off));
                acc1[k] = add2(acc1[k], __shfl_xor_sync(0xffffffffu, acc1[k], off));
            }
        }

        if (lane == 0) {
#pragma unroll
            for (int k = 0; k < 8; k++) {
                float lo, hi;
                unpack2(acc0[k], lo, hi);
                sOut[warp][0][2 * k]     = lo;
                sOut[warp][0][2 * k + 1] = hi;
                unpack2(acc1[k], lo, hi);
                sOut[warp][1][2 * k]     = lo;
                sOut[warp][1][2 * k + 1] = hi;
            }
        }
        __syncthreads();

        // ---- cross-warp sum + store --------------------------------------
        if (tid < cnt * 16) {
            const int s = tid >> 4;
            const int k = tid & 15;
            const float v = sOut[0][s][k] + sOut[1][s][k]
                          + sOut[2][s][k] + sOut[3][s][k];
            const int b = sItems[base + s] & 1023;
            out[((size_t)(t * BATCH + b)) * 16 + k] = v;
        }
        __syncthreads();   // protect sA/sOut before next group iteration
    }
}

extern "C" void kernel_launch(void* const* d_in, const int* in_sizes, int n_in,
                              void* d_out, int out_size)
{
    const void*  lS_i  = d_in[0];
    const float* core0 = (const float*)d_in[1];
    const float* core1 = (const float*)d_in[2];
    const float* core2 = (const float*)d_in[3];
    float*       out   = (float*)d_out;

    probe_dtype_kernel<<<1, 1>>>((const int*)lS_i);

    dim3 grid(NTAB * PDIM, YDIM);
    tt_bucket_kernel<<<grid, 128>>>(lS_i, core0, core1, core2, out);
}